// round 16
// baseline (speedup 1.0000x reference)
#include <cuda_runtime.h>

// DenseDilatedKnnGraph: x (4,64,8192,1) fp32 -> edge_index (2,4,8192,9)
// k=9, dilation=1. Output buffer FLOAT32 (confirmed).
//
// R16: 256-thread CTAs, per-thread 8 rows x 4 cands (acc=32 regs) -> 16
// warps/SM (was reg-capped at 12). q-tile stored DUPLICATED in smem ({q,q}
// u64) so the mainloop is pure LDS.128 + FFMA2 (no pack MOVs).

#define BB 4
#define DD 64
#define NN 8192
#define KK 9
#define CT 128         // candidates per tile
#define QT 64          // query rows per CTA
#define NTHR 256

typedef unsigned long long u64;

__device__ __align__(16) float g_ptsT[(size_t)BB * DD * NN];  // [b][d][n], 8 MB
__device__ float g_sq[BB * NN];

// smem layout (dynamic, 66048 B):
//   [0, 32768)      qs2: u64[64k][64r] = {q,q}   (merge bufs alias at end)
//   [32768, 65536)  cs : f32[64k][128c]          (d2 scratch aliases)
//   [65536, 66048)  csq: f32[128]
#define SMEM_BYTES (32768 + 32768 + 512)

__device__ __forceinline__ u64 ffma2(u64 a, u64 b, u64 c) {
    u64 d;
    asm("fma.rn.f32x2 %0, %1, %2, %3;" : "=l"(d) : "l"(a), "l"(b), "l"(c));
    return d;
}
__device__ __forceinline__ float2 unpack2(u64 a) {
    float2 f;
    asm("mov.b64 {%0, %1}, %2;" : "=f"(f.x), "=f"(f.y) : "l"(a));
    return f;
}

// ---------------------------------------------------------------------------
// Stage 1: normalize + transpose to [b][d][n]. One thread per point.
// ---------------------------------------------------------------------------
__global__ void __launch_bounds__(256) normalize_kernel(const float* __restrict__ x) {
    int idx = blockIdx.x * blockDim.x + threadIdx.x;
    if (idx >= BB * NN) return;
    int b = idx / NN;
    int n = idx - b * NN;
    const float* xb = x + (size_t)b * DD * NN + n;
    float* pb = g_ptsT + (size_t)b * DD * NN + n;

    float v[DD];
    float s = 0.0f;
#pragma unroll
    for (int d = 0; d < DD; d++) {
        v[d] = xb[(size_t)d * NN];
        s += v[d] * v[d];
    }
    float nrm = fmaxf(sqrtf(s), 1e-12f);
    float s2 = 0.0f;
#pragma unroll
    for (int d = 0; d < DD; d++) {
        float xn = v[d] / nrm;
        pb[(size_t)d * NN] = xn;
        s2 += xn * xn;
    }
    g_sq[idx] = s2;
}

// ---------------------------------------------------------------------------
// Stage 2: tiled KNN. Warp w owns rows w*8..+7; lane owns cands lane*4..+3.
// ---------------------------------------------------------------------------
__global__ void __launch_bounds__(NTHR, 2) knn_kernel(float* __restrict__ out) {
    extern __shared__ __align__(16) unsigned char smem_raw[];
    u64*   qs2 = (u64*)smem_raw;                     // 64*64 u64
    float* cs  = (float*)(smem_raw + 32768);         // 64*128 f32 (+ d2 alias)
    float* csq = (float*)(smem_raw + 65536);         // 128 f32
    float* md  = (float*)smem_raw;                   // merge dists [64][4][9]
    float* mi  = md + QT * 4 * KK;                   // merge idxs  [64][4][9]

    const int tid = threadIdx.x;
    const int w  = tid >> 5;          // warp 0..7 -> rows w*8..+7
    const int tx = tid & 31;          // lane     -> cands tx*4..+3
    const int blk = blockIdx.x;       // 0..511
    const int b = blk >> 7;
    const int q0 = (blk & 127) << 6;
    const float* __restrict__ ptsT = g_ptsT + (size_t)b * DD * NN;
    const size_t base = (size_t)b * NN;

    // build duplicated q tile: qs2[k*64 + r] = {q, q}
#pragma unroll
    for (int i = 0; i < 16; i++) {
        int e = tid + (i << 8);            // 0..4095
        int k = e >> 6, r = e & 63;
        float v = ptsT[(size_t)k * NN + q0 + r];
        ((float2*)qs2)[e] = make_float2(v, v);
    }
    float sqn[8];
#pragma unroll
    for (int r = 0; r < 8; r++) sqn[r] = g_sq[base + q0 + (w << 3) + r];

    // scan stream: thread = (row srow, quarter qtr); ascending idx -> stable
    const int srow = tid >> 2;
    const int qtr = tid & 3;
    float bd[KK];
    int   bi[KK];
#pragma unroll
    for (int i = 0; i < KK; i++) { bd[i] = 3.4e38f; bi[i] = 0; }

    u64 acc[16];                       // [r 0..7][candpair p 0..1]
#pragma unroll
    for (int i = 0; i < 16; i++) acc[i] = 0ull;

    for (int t0 = 0; t0 < NN; t0 += CT) {
        __syncthreads();               // prior scan done; cs reusable
#pragma unroll
        for (int i = 0; i < 8; i++) {
            int f = tid + (i << 8);        // 0..2047 float4
            int k = f >> 5, j4 = f & 31;
            ((float4*)cs)[f] = ((const float4*)(ptsT + (size_t)k * NN + t0))[j4];
        }
        if (tid < CT) csq[tid] = g_sq[base + t0 + tid];
        __syncthreads();

        // ---- mainloop: per k: 4 q-LDS.128 (broadcast) + 1 c-LDS.128,
        // 16 FFMA2, no MOVs.
        const u64* qb = qs2 + (w << 3);
        const float* cb = cs + (tx << 2);
#pragma unroll 4
        for (int k = 0; k < DD; k++) {
            const ulonglong2* qk = (const ulonglong2*)(qb + (k << 6));
            ulonglong2 q01 = qk[0], q23 = qk[1], q45 = qk[2], q67 = qk[3];
            ulonglong2 cp = *(const ulonglong2*)(cb + (k << 7));
#pragma unroll
            for (int r = 0; r < 8; r++) {
                u64 qd = r == 0 ? q01.x : r == 1 ? q01.y : r == 2 ? q23.x :
                         r == 3 ? q23.y : r == 4 ? q45.x : r == 5 ? q45.y :
                         r == 6 ? q67.x : q67.y;
                acc[r * 2 + 0] = ffma2(qd, cp.x, acc[r * 2 + 0]);
                acc[r * 2 + 1] = ffma2(qd, cp.y, acc[r * 2 + 1]);
            }
        }
        __syncthreads();               // all mainloop reads of cs done

        // ---- epilogue: d2 -> swizzled scratch aliasing cs.
        // word(r,c) = (r<<7) | ((c&3)<<5) | ((c>>2) ^ (r&7)).
        // scatter: c>>2 == tx -> bank = tx ^ const, conflict-free.
        float cq[4];
#pragma unroll
        for (int j = 0; j < 4; j++) cq[j] = csq[(tx << 2) + j];
#pragma unroll
        for (int r = 0; r < 8; r++) {
            int rg = (w << 3) + r;
            int rb = (rg << 7) + (tx ^ (rg & 7));
#pragma unroll
            for (int p = 0; p < 2; p++) {
                float2 d = unpack2(acc[r * 2 + p]);
                acc[r * 2 + p] = 0ull;
                float d2a = fmaxf((sqn[r] + cq[2 * p])     - 2.0f * d.x, 0.0f);
                float d2b = fmaxf((sqn[r] + cq[2 * p + 1]) - 2.0f * d.y, 0.0f);
                cs[rb + ((2 * p)     << 5)] = d2a;
                cs[rb + ((2 * p + 1) << 5)] = d2b;
            }
        }
        __syncthreads();

        // ---- scan: (srow, qtr) scans c = qtr*32 .. +31 ascending (stable).
#pragma unroll 4
        for (int j = 0; j < 32; j++) {
            int c = (qtr << 5) + j;
            float v = cs[(srow << 7) + ((j & 3) << 5) + (((qtr << 3) | (j >> 2)) ^ (srow & 7))];
            if (v < bd[KK - 1]) {
                float vv = v;
                int   vi = t0 + c;
#pragma unroll
                for (int s = 0; s < KK; s++) {
                    bool sw = vv < bd[s];
                    float tv = bd[s];
                    int   ti = bi[s];
                    if (sw) { bd[s] = vv; bi[s] = vi; vv = tv; vi = ti; }
                }
            }
        }
    }

    // ---- final 4-way merge per row; lists sorted by (d2, idx).
    __syncthreads();                   // qs2 dead -> merge buffers
    {
        int slot = ((srow << 2) | qtr) * KK;
#pragma unroll
        for (int i = 0; i < KK; i++) {
            md[slot + i] = bd[i];
            mi[slot + i] = (float)bi[i];
        }
    }
    __syncthreads();

    if (tid < QT) {
        const float* Ld = md + (tid << 2) * KK;
        const float* Li = mi + (tid << 2) * KK;
        int p0 = 0, p1 = 0, p2 = 0, p3 = 0;
        const size_t o = (base + q0 + tid) * KK;
#pragma unroll
        for (int i = 0; i < KK; i++) {
            float d0 = Ld[p0], d1 = Ld[KK + p1], d2v = Ld[2 * KK + p2], d3 = Ld[3 * KK + p3];
            float i0 = Li[p0], i1 = Li[KK + p1], i2v = Li[2 * KK + p2], i3 = Li[3 * KK + p3];
            // lexicographic (d, idx) min of 4 heads (tie -> lower idx)
            bool a01 = (d0 < d1) || (d0 == d1 && i0 < i1);
            float da = a01 ? d0 : d1, ia = a01 ? i0 : i1;
            bool a23 = (d2v < d3) || (d2v == d3 && i2v < i3);
            float db2 = a23 ? d2v : d3, ib2 = a23 ? i2v : i3;
            bool af = (da < db2) || (da == db2 && ia < ib2);
            float dw = af ? da : db2, iw = af ? ia : ib2;
            out[o + i] = iw;
            // advance the winning list
            p0 += (dw == d0 && iw == i0) ? 1 : 0;
            p1 += (dw == d1 && iw == i1 && !(dw == d0 && iw == i0)) ? 1 : 0;
            p2 += (dw == d2v && iw == i2v && !(dw == d0 && iw == i0) && !(dw == d1 && iw == i1)) ? 1 : 0;
            p3 += (dw == d3 && iw == i3 && !(dw == d0 && iw == i0) && !(dw == d1 && iw == i1) && !(dw == d2v && iw == i2v)) ? 1 : 0;
            out[(size_t)BB * NN * KK + o + i] = (float)(q0 + tid);
        }
    }
}

extern "C" void kernel_launch(void* const* d_in, const int* in_sizes, int n_in,
                              void* d_out, int out_size) {
    int best = 0, best_sz = -1;
    for (int i = 0; i < n_in; i++) {
        if (in_sizes[i] == BB * DD * NN) { best = i; best_sz = in_sizes[i]; break; }
        if (in_sizes[i] > best_sz) { best_sz = in_sizes[i]; best = i; }
    }
    const float* x = (const float*)d_in[best];
    float* out = (float*)d_out;

    cudaFuncSetAttribute(knn_kernel, cudaFuncAttributeMaxDynamicSharedMemorySize,
                         SMEM_BYTES);
    normalize_kernel<<<(BB * NN + 255) / 256, 256>>>(x);
    knn_kernel<<<(BB * NN) / QT, NTHR, SMEM_BYTES>>>(out);
}

// round 17
// speedup vs baseline: 1.1939x; 1.1939x over previous
#include <cuda_runtime.h>

// DenseDilatedKnnGraph: x (4,64,8192,1) fp32 -> edge_index (2,4,8192,9)
// k=9, dilation=1. Output buffer FLOAT32 (confirmed).
//
// R17: TF32 tensor cores (legacy mma.sync m16n8k8) with 3-term precision
// split: dot = xh*yh + xh*yl + xl*yh  (xh=tf32(x), xl=tf32(x-xh)),
// error ~2^-22 ~ fp32 reorder noise -> same tie behavior as the passing
// fp32 kernels (rel_err 2.7e-4). Cands=A(m), queries=B(n); A-frags and all
// C blocks register-resident; conflict-free smem strides (72/68).

#define BB 4
#define DD 64
#define NN 8192
#define KK 9
#define CT 64          // candidates per tile (A side, m)
#define QT 64          // queries per CTA (B side, n)
#define NTHR 128       // 4 warps; warp w owns cand rows 16w..16w+15
#define SQS 72         // query smem row stride (floats): conflict-free frags
#define SCS 72         // cand  smem row stride
#define SDS 68         // d2 scratch row stride

__device__ __align__(16) float g_hi[(size_t)BB * DD * NN];  // tf32 hi, [b][d][n]
__device__ __align__(16) float g_lo[(size_t)BB * DD * NN];  // tf32 lo
__device__ float g_sq[BB * NN];

// smem (floats): qh | ql | ch | cl | csq | qsq
#define OFF_QH 0
#define OFF_QL (OFF_QH + DD * SQS)       // 4608
#define OFF_CH (OFF_QL + DD * SQS)       // 9216  (d2 scratch aliases: 64*68=4352)
#define OFF_CL (OFF_CH + DD * SCS)       // 13824 (merge bufs alias: 2304)
#define OFF_CSQ (OFF_CL + DD * SCS)      // 18432
#define OFF_QSQ (OFF_CSQ + CT)           // 18496
#define SMEM_FLOATS (OFF_QSQ + QT)       // 18560
#define SMEM_BYTES (SMEM_FLOATS * 4)     // 74240 -> 3 CTAs/SM (222.7 KB)

__device__ __forceinline__ unsigned f2tf32(float x) {
    unsigned u;
    asm("cvt.rna.tf32.f32 %0, %1;" : "=r"(u) : "f"(x));
    return u;
}
__device__ __forceinline__ void mma_tf32(float& c0, float& c1, float& c2, float& c3,
                                         unsigned a0, unsigned a1, unsigned a2, unsigned a3,
                                         unsigned b0, unsigned b1) {
    asm("mma.sync.aligned.m16n8k8.row.col.f32.tf32.tf32.f32 "
        "{%0,%1,%2,%3}, {%4,%5,%6,%7}, {%8,%9}, {%0,%1,%2,%3};"
        : "+f"(c0), "+f"(c1), "+f"(c2), "+f"(c3)
        : "r"(a0), "r"(a1), "r"(a2), "r"(a3), "r"(b0), "r"(b1));
}

// ---------------------------------------------------------------------------
// Stage 1: normalize, split to tf32 hi/lo planes [b][d][n], store sq.
// ---------------------------------------------------------------------------
__global__ void __launch_bounds__(256) normalize_kernel(const float* __restrict__ x) {
    int idx = blockIdx.x * blockDim.x + threadIdx.x;
    if (idx >= BB * NN) return;
    int b = idx / NN;
    int n = idx - b * NN;
    const float* xb = x + (size_t)b * DD * NN + n;
    float* ph = g_hi + (size_t)b * DD * NN + n;
    float* pl = g_lo + (size_t)b * DD * NN + n;

    float v[DD];
    float s = 0.0f;
#pragma unroll
    for (int d = 0; d < DD; d++) {
        v[d] = xb[(size_t)d * NN];
        s += v[d] * v[d];
    }
    float nrm = fmaxf(sqrtf(s), 1e-12f);   // F.normalize eps
    float s2 = 0.0f;
#pragma unroll
    for (int d = 0; d < DD; d++) {
        float xn = v[d] / nrm;
        s2 += xn * xn;
        float hi = __uint_as_float(f2tf32(xn));
        float lo = __uint_as_float(f2tf32(xn - hi));
        ph[(size_t)d * NN] = hi;
        pl[(size_t)d * NN] = lo;
    }
    g_sq[idx] = s2;
}

// ---------------------------------------------------------------------------
// Stage 2: KNN via TF32 MMA tiles + per-row top-9 (stable).
// ---------------------------------------------------------------------------
__global__ void __launch_bounds__(NTHR, 3) knn_kernel(float* __restrict__ out) {
    extern __shared__ __align__(16) float sm[];
    float* qh = sm + OFF_QH;
    float* ql = sm + OFF_QL;
    float* ch = sm + OFF_CH;     // also d2 scratch
    float* cl = sm + OFF_CL;     // also merge buffers
    float* csq = sm + OFF_CSQ;
    float* qsq = sm + OFF_QSQ;

    const int tid = threadIdx.x;
    const int w = tid >> 5, lane = tid & 31;
    const int la3 = lane & 3, c8 = lane >> 2;
    const int blk = blockIdx.x;        // 0..511
    const int b = blk >> 7;
    const int q0 = (blk & 127) << 6;
    const size_t base = (size_t)b * NN;
    const float* __restrict__ Ghi = g_hi + (size_t)b * DD * NN;
    const float* __restrict__ Glo = g_lo + (size_t)b * DD * NN;

    // ---- stage queries (once per CTA): [k][q] hi/lo, stride SQS
#pragma unroll
    for (int i = 0; i < 8; i++) {
        int f = tid + (i << 7);            // 0..1023
        int k = f >> 4, c4 = f & 15;
        *(float4*)(qh + k * SQS + 4 * c4) =
            *(const float4*)(Ghi + (size_t)k * NN + q0 + 4 * c4);
        *(float4*)(ql + k * SQS + 4 * c4) =
            *(const float4*)(Glo + (size_t)k * NN + q0 + 4 * c4);
    }
    if (tid < QT) qsq[tid] = g_sq[base + q0 + tid];

    // per-thread scan stream: query (tid>>1), candidate half (tid&1)
    const int srow = tid >> 1;
    const int half = tid & 1;
    float bd[KK];
    int   bi[KK];
#pragma unroll
    for (int i = 0; i < KK; i++) { bd[i] = 3.4e38f; bi[i] = 0; }

    for (int t0 = 0; t0 < NN; t0 += CT) {
        __syncthreads();               // prev scan done; ch/cl reusable
        // ---- stage candidate tile [k][c] hi/lo
#pragma unroll
        for (int i = 0; i < 8; i++) {
            int f = tid + (i << 7);
            int k = f >> 4, c4 = f & 15;
            *(float4*)(ch + k * SCS + 4 * c4) =
                *(const float4*)(Ghi + (size_t)k * NN + t0 + 4 * c4);
            *(float4*)(cl + k * SCS + 4 * c4) =
                *(const float4*)(Glo + (size_t)k * NN + t0 + 4 * c4);
        }
        if (tid < CT) csq[tid] = g_sq[base + t0 + tid];
        __syncthreads();

        // ---- A fragments (cands, rows 16w..16w+15) hi+lo: register resident
        unsigned Ah[32], Al[32];
#pragma unroll
        for (int kb = 0; kb < 8; kb++) {
            int ar = (kb * 8 + la3) * SCS + 16 * w + c8;
            Ah[kb * 4 + 0] = __float_as_uint(ch[ar]);
            Ah[kb * 4 + 1] = __float_as_uint(ch[ar + 8]);
            Ah[kb * 4 + 2] = __float_as_uint(ch[ar + 4 * SCS]);
            Ah[kb * 4 + 3] = __float_as_uint(ch[ar + 4 * SCS + 8]);
            Al[kb * 4 + 0] = __float_as_uint(cl[ar]);
            Al[kb * 4 + 1] = __float_as_uint(cl[ar + 8]);
            Al[kb * 4 + 2] = __float_as_uint(cl[ar + 4 * SCS]);
            Al[kb * 4 + 3] = __float_as_uint(cl[ar + 4 * SCS + 8]);
        }

        float C[32];                   // 8 n-blocks x 4
#pragma unroll
        for (int i = 0; i < 32; i++) C[i] = 0.0f;

        // ---- mainloop: 3-term tf32: C += Ah*Bh + Ah*Bl + Al*Bh
#pragma unroll
        for (int kb = 0; kb < 8; kb++) {
            unsigned Bh[16];
#pragma unroll
            for (int nb = 0; nb < 8; nb++) {
                int br = (kb * 8 + la3) * SQS + 8 * nb + c8;
                Bh[nb * 2]     = __float_as_uint(qh[br]);
                Bh[nb * 2 + 1] = __float_as_uint(qh[br + 4 * SQS]);
                mma_tf32(C[nb*4], C[nb*4+1], C[nb*4+2], C[nb*4+3],
                         Ah[kb*4], Ah[kb*4+1], Ah[kb*4+2], Ah[kb*4+3],
                         Bh[nb*2], Bh[nb*2+1]);
            }
#pragma unroll
            for (int nb = 0; nb < 8; nb++) {
                int br = (kb * 8 + la3) * SQS + 8 * nb + c8;
                unsigned bl0 = __float_as_uint(ql[br]);
                unsigned bl1 = __float_as_uint(ql[br + 4 * SQS]);
                mma_tf32(C[nb*4], C[nb*4+1], C[nb*4+2], C[nb*4+3],
                         Ah[kb*4], Ah[kb*4+1], Ah[kb*4+2], Ah[kb*4+3],
                         bl0, bl1);
            }
#pragma unroll
            for (int nb = 0; nb < 8; nb++) {
                mma_tf32(C[nb*4], C[nb*4+1], C[nb*4+2], C[nb*4+3],
                         Al[kb*4], Al[kb*4+1], Al[kb*4+2], Al[kb*4+3],
                         Bh[nb*2], Bh[nb*2+1]);
            }
        }
        __syncthreads();               // all frag reads done; ch -> d2 scratch

        // ---- epilogue: C -> d2 -> scratch[q][cand], stride SDS (conflict-free)
        // c0:(cand_r, q_c) c1:(cand_r, q_c+1) c2:(cand_r+8, q_c) c3:(+8,+1)
        {
            int cand_r = 16 * w + c8;
            float csa = csq[cand_r], csb = csq[cand_r + 8];
#pragma unroll
            for (int nb = 0; nb < 8; nb++) {
                int q_c = 8 * nb + 2 * la3;
                float qa = qsq[q_c], qb = qsq[q_c + 1];
                float* s0 = ch + q_c * SDS + cand_r;
                s0[0]        = fmaxf((qa + csa) - 2.0f * C[nb*4+0], 0.0f);
                s0[SDS]      = fmaxf((qb + csa) - 2.0f * C[nb*4+1], 0.0f);
                s0[8]        = fmaxf((qa + csb) - 2.0f * C[nb*4+2], 0.0f);
                s0[SDS + 8]  = fmaxf((qb + csb) - 2.0f * C[nb*4+3], 0.0f);
            }
        }
        __syncthreads();

        // ---- scan: (srow, half) scans cands half*32..+31 ascending (stable)
#pragma unroll 4
        for (int j = 0; j < 32; j++) {
            int c = (half << 5) + j;
            float v = ch[srow * SDS + c];
            if (v < bd[KK - 1]) {
                float vv = v;
                int   vi = t0 + c;
#pragma unroll
                for (int s = 0; s < KK; s++) {
                    bool sw = vv < bd[s];
                    float tv = bd[s];
                    int   ti = bi[s];
                    if (sw) { bd[s] = vv; bi[s] = vi; vv = tv; vi = ti; }
                }
            }
        }
    }

    // ---- merge the two per-row half-lists (sorted by (d2, idx)).
    __syncthreads();                   // cl dead -> merge buffers
    float* md = cl;                    // [64][2][9] distances
    float* mi = cl + QT * 2 * KK;      // [64][2][9] indices
    {
        int slot = ((srow << 1) + half) * KK;
#pragma unroll
        for (int i = 0; i < KK; i++) {
            md[slot + i] = bd[i];
            mi[slot + i] = (float)bi[i];
        }
    }
    __syncthreads();

    if (tid < QT) {
        const float* dA = md + (tid << 1) * KK;
        const float* dB = dA + KK;
        const float* iA = mi + (tid << 1) * KK;
        const float* iB = iA + KK;
        const size_t o = (base + q0 + tid) * KK;
        int pa = 0, pb = 0;
#pragma unroll
        for (int i = 0; i < KK; i++) {
            float da = dA[pa], db = dB[pb];
            float ia = iA[pa], ib = iB[pb];
            bool takeA = (da < db) || (da == db && ia < ib);  // tie: lower idx
            out[o + i] = takeA ? ia : ib;
            pa += takeA ? 1 : 0;
            pb += takeA ? 0 : 1;
            out[(size_t)BB * NN * KK + o + i] = (float)(q0 + tid);
        }
    }
}

extern "C" void kernel_launch(void* const* d_in, const int* in_sizes, int n_in,
                              void* d_out, int out_size) {
    int best = 0, best_sz = -1;
    for (int i = 0; i < n_in; i++) {
        if (in_sizes[i] == BB * DD * NN) { best = i; best_sz = in_sizes[i]; break; }
        if (in_sizes[i] > best_sz) { best_sz = in_sizes[i]; best = i; }
    }
    const float* x = (const float*)d_in[best];
    float* out = (float*)d_out;

    cudaFuncSetAttribute(knn_kernel, cudaFuncAttributeMaxDynamicSharedMemorySize,
                         SMEM_BYTES);
    normalize_kernel<<<(BB * NN + 255) / 256, 256>>>(x);
    knn_kernel<<<(BB * NN) / QT, NTHR, SMEM_BYTES>>>(out);
}